// round 15
// baseline (speedup 1.0000x reference)
#include <cuda_runtime.h>
#include <cuda_fp16.h>
#include <math.h>
#include <stdint.h>

// ---------------------------------------------------------------------------
// Problem constants
// ---------------------------------------------------------------------------
#define Bc    2
#define Sc    2048
#define HIDc  4096
#define Hc    32
#define KVc   8
#define Dc    128
#define Wc    512
#define BSc   (Bc * Sc)              // 4096
#define QKVF  ((Hc + 2 * KVc) * Dc)  // 6144

// global operand scale 2^10
#define SCF      1024.0f
#define INV_SC2  (1.0f / (SCF * SCF))
#define INV_SCF  (1.0f / SCF)
#define LOG2E    1.4426950408889634f

// ---------------------------------------------------------------------------
// Scratch (static device globals -- no allocation allowed)
// ---------------------------------------------------------------------------
__device__ __half g_qkvh[(size_t)BSc * QKVF];            // scaled fp16 qkv

__device__ __half g_qh[(size_t)BSc * Hc * Dc];           // roped Q [bs][h][d]
__device__ __half g_kh[(size_t)BSc * KVc * Dc];          // K [bs][kv][d]
__device__ __half g_vh[(size_t)BSc * KVc * Dc];          // V [bs][kv][d]

__device__ __half g_ah[(size_t)BSc * HIDc];              // GEMM A [M,K]
__device__ __half g_bh[(size_t)QKVF * HIDc];             // GEMM B [K,N]

// ---------------------------------------------------------------------------
// Helpers
// ---------------------------------------------------------------------------
__device__ __forceinline__ uint32_t smem_u32(const void* p) {
    uint32_t a;
    asm("{ .reg .u64 t; cvta.to.shared.u64 t, %1; cvt.u32.u64 %0, t; }"
        : "=r"(a) : "l"(p));
    return a;
}
__device__ __forceinline__ void cp16(uint32_t smem, const void* gmem) {
    asm volatile("cp.async.cg.shared.global [%0], [%1], 16;"
                 :: "r"(smem), "l"(gmem));
}
#define CP_COMMIT() asm volatile("cp.async.commit_group;" ::: "memory")
#define CP_WAIT0()  asm volatile("cp.async.wait_group 0;" ::: "memory")

__device__ __forceinline__ void ldsm_x4(uint32_t* r, uint32_t addr) {
    asm volatile("ldmatrix.sync.aligned.m8n8.x4.shared.b16 {%0,%1,%2,%3}, [%4];"
                 : "=r"(r[0]), "=r"(r[1]), "=r"(r[2]), "=r"(r[3]) : "r"(addr));
}
__device__ __forceinline__ void ldsm_x4_t(uint32_t* r, uint32_t addr) {
    asm volatile("ldmatrix.sync.aligned.m8n8.x4.trans.shared.b16 {%0,%1,%2,%3}, [%4];"
                 : "=r"(r[0]), "=r"(r[1]), "=r"(r[2]), "=r"(r[3]) : "r"(addr));
}

// fp16 HMMA m16n8k16, fp32 accumulate
__device__ __forceinline__ void mma16816(float* d, const uint32_t* a,
                                         const uint32_t* b) {
    asm volatile(
        "mma.sync.aligned.m16n8k16.row.col.f32.f16.f16.f32 "
        "{%0,%1,%2,%3}, {%4,%5,%6,%7}, {%8,%9}, {%0,%1,%2,%3};"
        : "+f"(d[0]), "+f"(d[1]), "+f"(d[2]), "+f"(d[3])
        : "r"(a[0]), "r"(a[1]), "r"(a[2]), "r"(a[3]),
          "r"(b[0]), "r"(b[1]));
}

__device__ __forceinline__ uint32_t packh2(float x, float y) {
    __half2 h(__float2half_rn(x), __float2half_rn(y));
    return *(uint32_t*)&h;
}

// ---------------------------------------------------------------------------
// fp16 HMMA GEMM, templated epilogue (unchanged from R14 passing version)
// ---------------------------------------------------------------------------
#define GBK    64
#define AROW   144
#define BROW   272
#define MAT_A  (128 * AROW)
#define MAT_B  (64 * BROW)
#define STAGEB (MAT_A + MAT_B)
#define GEMM_SMEM (2 * STAGEB)

template <bool HOUT>
__global__ __launch_bounds__(256, 2)
void gemm_mma(const __half* __restrict__ Ah,
              const __half* __restrict__ Bh,
              void* __restrict__ Cv, int M, int N, int K)
{
    extern __shared__ char sm[];
    const uint32_t sb = smem_u32(sm);
    const int tid  = threadIdx.x;
    const int wid  = tid >> 5;
    const int lane = tid & 31;
    const int wm = wid & 3;
    const int wn = wid >> 2;
    const int g  = lane >> 2;
    const int tg = lane & 3;

    const int m0 = blockIdx.y * 128;
    const int n0 = blockIdx.x * 128;

    const uint32_t amrow = (lane & 7) + ((lane >> 3) & 1) * 8;
    const uint32_t acol  = (uint32_t)(lane >> 4) * 16;
    const uint32_t bkrow = (lane & 7) + ((lane >> 3) & 1) * 8;
    const uint32_t bncol = (uint32_t)(lane >> 4) * 16;

    auto load_stage = [&](int k0, int st) {
        const uint32_t base = sb + st * STAGEB;
#pragma unroll
        for (int hh = 0; hh < 4; hh++) {
            int unit = tid + hh * 256;
            int r = unit >> 3, u = unit & 7;
            const void* gp = Ah + (size_t)(m0 + r) * K + k0 + u * 8;
            cp16(base + r * AROW + u * 16, gp);
        }
#pragma unroll
        for (int hh = 0; hh < 4; hh++) {
            int unit = tid + hh * 256;
            int r = unit >> 4, u = unit & 15;
            const void* gp = Bh + (size_t)(k0 + r) * N + n0 + u * 8;
            cp16(base + MAT_A + r * BROW + u * 16, gp);
        }
    };

    float acc[2][8][4];
#pragma unroll
    for (int mt = 0; mt < 2; mt++)
#pragma unroll
        for (int nt = 0; nt < 8; nt++)
#pragma unroll
            for (int j = 0; j < 4; j++) acc[mt][nt][j] = 0.f;

    const int NIT = K / GBK;
    load_stage(0, 0);
    CP_COMMIT();

    for (int it = 0; it < NIT; it++) {
        CP_WAIT0();
        __syncthreads();
        const int st = it & 1;
        if (it + 1 < NIT) {
            load_stage((it + 1) * GBK, st ^ 1);
            CP_COMMIT();
        }

        const uint32_t ahb = sb + st * STAGEB;
        const uint32_t bhb = ahb + MAT_A;

#pragma unroll
        for (int ks = 0; ks < 4; ks++) {
            uint32_t ah[2][4];
#pragma unroll
            for (int mt = 0; mt < 2; mt++) {
                const uint32_t ar = ahb +
                    (uint32_t)((wm * 32 + mt * 16 + amrow) * AROW) +
                    (uint32_t)(ks * 32) + acol;
                ldsm_x4(ah[mt], ar);
            }
#pragma unroll
            for (int ntp = 0; ntp < 4; ntp++) {
                const uint32_t br = bhb +
                    (uint32_t)((ks * 16 + bkrow) * BROW) +
                    (uint32_t)((wn * 64 + ntp * 16) * 2) + bncol;
                uint32_t bh4[4];
                ldsm_x4_t(bh4, br);
#pragma unroll
                for (int mt = 0; mt < 2; mt++) {
                    mma16816(acc[mt][2 * ntp],     ah[mt], &bh4[0]);
                    mma16816(acc[mt][2 * ntp + 1], ah[mt], &bh4[2]);
                }
            }
        }
    }

#pragma unroll
    for (int mt = 0; mt < 2; mt++) {
        const int r0 = m0 + wm * 32 + mt * 16 + g;
#pragma unroll
        for (int nt = 0; nt < 8; nt++) {
            const int cc = n0 + wn * 64 + nt * 8 + tg * 2;
            if (HOUT) {
                __half* cp = (__half*)Cv;
                *(uint32_t*)(cp + (size_t)r0 * N + cc) =
                    packh2(acc[mt][nt][0] * INV_SCF, acc[mt][nt][1] * INV_SCF);
                *(uint32_t*)(cp + (size_t)(r0 + 8) * N + cc) =
                    packh2(acc[mt][nt][2] * INV_SCF, acc[mt][nt][3] * INV_SCF);
            } else {
                float* cp = (float*)Cv;
                float2 w0 = make_float2(acc[mt][nt][0] * INV_SC2,
                                        acc[mt][nt][1] * INV_SC2);
                float2 w1 = make_float2(acc[mt][nt][2] * INV_SC2,
                                        acc[mt][nt][3] * INV_SC2);
                *(float2*)(cp + (size_t)r0 * N + cc)       = w0;
                *(float2*)(cp + (size_t)(r0 + 8) * N + cc) = w1;
            }
        }
    }
}

// ---------------------------------------------------------------------------
// Fused input conversion: hidden -> g_ah, w_pack -> g_bh
// ---------------------------------------------------------------------------
#define N4_HID  (BSc * HIDc / 4)
#define NB_HID  (N4_HID / 256)               // 16384
#define N4_WP   (HIDc * QKVF / 4)
#define NB_WP   (N4_WP / 256)                // 24576

__global__ void conv_in_kernel(const float* __restrict__ hidden,
                               const float* __restrict__ w_pack,
                               __half* __restrict__ Ah,
                               __half* __restrict__ Bh)
{
    int bid = blockIdx.x;
    if (bid < NB_HID) {
        int i = bid * 256 + threadIdx.x;
        float4 v = ((const float4*)hidden)[i];
        ((uint32_t*)Ah)[i * 2 + 0] = packh2(v.x * SCF, v.y * SCF);
        ((uint32_t*)Ah)[i * 2 + 1] = packh2(v.z * SCF, v.w * SCF);
    } else {
        int i = (bid - NB_HID) * 256 + threadIdx.x;
        float4 v = ((const float4*)w_pack)[i];
        ((uint32_t*)Bh)[i * 2 + 0] = packh2(v.x * SCF, v.y * SCF);
        ((uint32_t*)Bh)[i * 2 + 1] = packh2(v.z * SCF, v.w * SCF);
    }
}

// ---------------------------------------------------------------------------
// Fused prep from scaled-fp16 qkv (unchanged from R14 passing version)
// ---------------------------------------------------------------------------
#define NB_Q   (BSc * Hc * 16 / 256)         // 8192
#define NB_K   (BSc * KVc * 16 / 256)        // 2048
#define NB_V   (BSc * KVc * 16 / 256)        // 2048
#define N4_WO  (HIDc * HIDc / 4)
#define NB_WO  (N4_WO / 256)                 // 16384

__global__ void fused_prep_kernel(const __half* __restrict__ qkvh,
                                  const int* __restrict__ positions,
                                  const float* __restrict__ conv_k,
                                  const float* __restrict__ conv_v,
                                  const float* __restrict__ w_o,
                                  __half* __restrict__ Qh,
                                  __half* __restrict__ Kh,
                                  __half* __restrict__ Vh,
                                  __half* __restrict__ Bh)
{
    int bid = blockIdx.x;
    if (bid < NB_Q) {
        int idx = bid * 256 + threadIdx.x;
        int t  = idx & 15;
        int h  = (idx >> 4) & 31;
        int bs = idx >> 9;

        const __half* src = qkvh + (size_t)bs * QKVF + h * Dc;
        uint2 a = *(const uint2*)(src + t * 4);
        uint2 c = *(const uint2*)(src + t * 4 + 64);
        const __half* ah = (const __half*)&a;
        const __half* ch = (const __half*)&c;
        float pos = (float)positions[bs];

        uint32_t o1[2], o2[2];
#pragma unroll
        for (int j2 = 0; j2 < 2; j2++) {
            float y1[2], y2[2];
#pragma unroll
            for (int j = 0; j < 2; j++) {
                int i = t * 4 + j2 * 2 + j;
                float x1 = __half2float(ah[j2 * 2 + j]);
                float x2 = __half2float(ch[j2 * 2 + j]);
                float ang = pos * exp2f((float)i * -0.2076205059304601f);
                float sn, cs;
                sincosf(ang, &sn, &cs);
                y1[j] = x1 * cs - x2 * sn;
                y2[j] = x2 * cs + x1 * sn;
            }
            o1[j2] = packh2(y1[0], y1[1]);
            o2[j2] = packh2(y2[0], y2[1]);
        }
        size_t o = (size_t)bs * (Hc * Dc) + h * Dc;
        *(uint2*)(Qh + o + t * 4)      = make_uint2(o1[0], o1[1]);
        *(uint2*)(Qh + o + t * 4 + 64) = make_uint2(o2[0], o2[1]);
    } else if (bid < NB_Q + NB_K) {
        int idx = (bid - NB_Q) * 256 + threadIdx.x;
        int t  = idx & 15;
        int kv = (idx >> 4) & 7;
        int bs = idx >> 7;
        int s = bs & (Sc - 1);

        const __half* src = qkvh + (size_t)bs * QKVF + Hc * Dc + kv * Dc;
        uint2 a = *(const uint2*)(src + t * 4);
        uint2 c = *(const uint2*)(src + t * 4 + 64);
        uint2 pa = make_uint2(0, 0), pc = make_uint2(0, 0);
        if (s > 0) {
            pa = *(const uint2*)(src - QKVF + t * 4);
            pc = *(const uint2*)(src - QKVF + t * 4 + 64);
        }
        const __half* ah = (const __half*)&a;
        const __half* ch = (const __half*)&c;
        const __half* pah = (const __half*)&pa;
        const __half* pch = (const __half*)&pc;
        float f0 = conv_k[kv], f1 = conv_k[KVc + kv];
        float pos = (float)positions[bs];

        uint32_t o1[2], o2[2];
#pragma unroll
        for (int j2 = 0; j2 < 2; j2++) {
            float y1[2], y2[2];
#pragma unroll
            for (int j = 0; j < 2; j++) {
                int i = t * 4 + j2 * 2 + j;
                float x1 = __half2float(ah[j2 * 2 + j]) * f1 +
                           __half2float(pah[j2 * 2 + j]) * f0;
                float x2 = __half2float(ch[j2 * 2 + j]) * f1 +
                           __half2float(pch[j2 * 2 + j]) * f0;
                float ang = pos * exp2f((float)i * -0.2076205059304601f);
                float sn, cs;
                sincosf(ang, &sn, &cs);
                y1[j] = x1 * cs - x2 * sn;
                y2[j] = x2 * cs + x1 * sn;
            }
            o1[j2] = packh2(y1[0], y1[1]);
            o2[j2] = packh2(y2[0], y2[1]);
        }
        size_t o = ((size_t)bs * KVc + kv) * Dc;
        *(uint2*)(Kh + o + t * 4)      = make_uint2(o1[0], o1[1]);
        *(uint2*)(Kh + o + t * 4 + 64) = make_uint2(o2[0], o2[1]);
    } else if (bid < NB_Q + NB_K + NB_V) {
        int idx = (bid - NB_Q - NB_K) * 256 + threadIdx.x;
        int t  = idx & 15;
        int kv = (idx >> 4) & 7;
        int bs = idx >> 7;
        int s = bs & (Sc - 1);

        const __half* src = qkvh + (size_t)bs * QKVF + (Hc + KVc) * Dc + kv * Dc;
        uint4 cu = *(const uint4*)(src + t * 8);
        uint4 pu = make_uint4(0, 0, 0, 0);
        if (s > 0) pu = *(const uint4*)(src - QKVF + t * 8);
        const __half* chh = (const __half*)&cu;
        const __half* phh = (const __half*)&pu;
        float f0 = conv_v[kv], f1 = conv_v[KVc + kv];

        uint32_t ow[4];
#pragma unroll
        for (int j2 = 0; j2 < 4; j2++) {
            float v0 = __half2float(chh[j2 * 2])     * f1 +
                       __half2float(phh[j2 * 2])     * f0;
            float v1 = __half2float(chh[j2 * 2 + 1]) * f1 +
                       __half2float(phh[j2 * 2 + 1]) * f0;
            ow[j2] = packh2(v0, v1);
        }
        size_t o = ((size_t)bs * KVc + kv) * Dc + t * 8;
        *(uint4*)(Vh + o) = make_uint4(ow[0], ow[1], ow[2], ow[3]);
    } else {
        int i = (bid - NB_Q - NB_K - NB_V) * 256 + threadIdx.x;
        float4 v = ((const float4*)w_o)[i];
        ((uint32_t*)Bh)[i * 2 + 0] = packh2(v.x * SCF, v.y * SCF);
        ((uint32_t*)Bh)[i * 2 + 1] = packh2(v.z * SCF, v.w * SCF);
    }
}

// ---------------------------------------------------------------------------
// Register-resident windowed flash attention, fp16.
// R15 change: Q fragments reloaded from smem per k-tile (no persistent qfh),
// __launch_bounds__(128, 3) -> 170-reg cap -> 12 warps/SM target.
// ---------------------------------------------------------------------------
#define RQK  272

#define A_QH   0
#define A_ST0  (A_QH + 64 * RQK)
#define KV_STAGE (2 * 64 * RQK)
#define ST_KH  0
#define ST_VH  (64 * RQK)
#define ATTN_SMEM (A_ST0 + 2 * KV_STAGE)            // 87040 -> fits 2/SM by smem

__global__ __launch_bounds__(128, 3)
void attn_mma(const __half* __restrict__ Qh,
              const __half* __restrict__ Kh, const __half* __restrict__ Vh,
              __half* __restrict__ Oh)
{
    extern __shared__ char sm[];
    const uint32_t sb = smem_u32(sm);

    const int tid  = threadIdx.x;
    const int w    = tid >> 5;
    const int lane = tid & 31;
    const int g  = lane >> 2;
    const int tg = lane & 3;

    const int qt = blockIdx.x, h = blockIdx.y, b = blockIdx.z;
    const int q0 = qt * 64;
    const int kvh = h >> 2;
    const float scale_eff = 0.08838834764831845f * INV_SC2 * LOG2E;

    const uint32_t bmrow = (lane & 7) + (uint32_t)(lane >> 4) * 8;
    const uint32_t bcol  = ((lane >> 3) & 1) * 16;
    const uint32_t vkrow = (lane & 7) + ((lane >> 3) & 1) * 8;
    const uint32_t vncol = (uint32_t)(lane >> 4) * 16;
    const uint32_t amrow = (lane & 7) + ((lane >> 3) & 1) * 8;
    const uint32_t acol  = (uint32_t)(lane >> 4) * 16;
    // precomputed base of this warp's Q fragment rows in smem
    const uint32_t qfbase = sb + A_QH + (uint32_t)((w * 16 + amrow) * RQK) + acol;

    // ---- load Q tile (64 rows) via cp.async ----
    {
        const size_t qbase = ((size_t)(b * Sc + q0) * Hc + h) * Dc;
#pragma unroll
        for (int hh = 0; hh < 8; hh++) {
            int idx = tid + hh * 128;
            int r = idx >> 4, u = idx & 15;
            const size_t go = qbase + (size_t)r * (Hc * Dc) + u * 8;
            cp16(sb + A_QH + r * RQK + u * 16, Qh + go);
        }
    }

    const size_t kvbase = ((size_t)b * Sc * KVc + kvh) * Dc;
    auto load_kv = [&](int kt, int st) {
        const int k0 = kt * 64;
        const uint32_t stb = sb + A_ST0 + st * KV_STAGE;
#pragma unroll
        for (int hh = 0; hh < 8; hh++) {
            int idx = tid + hh * 128;
            int r = idx >> 4, u = idx & 15;
            const size_t go = kvbase + (size_t)(k0 + r) * (KVc * Dc) + u * 8;
            cp16(stb + ST_KH + r * RQK + u * 16, Kh + go);
            cp16(stb + ST_VH + r * RQK + u * 16, Vh + go);
        }
    };

    float m0 = -1e30f, m1 = -1e30f, l0 = 0.f, l1 = 0.f;
    float oacc[16][4];
#pragma unroll
    for (int nt = 0; nt < 16; nt++)
#pragma unroll
        for (int j = 0; j < 4; j++) oacc[nt][j] = 0.f;

    const int qw_lo = q0 + w * 16;
    const int qw_hi = qw_lo + 15;
    const int qi0 = qw_lo + g;
    const int qi1 = qi0 + 8;

    int kt_lo = qt - 8; if (kt_lo < 0) kt_lo = 0;
    const int kt_hi = qt;

    load_kv(kt_lo, 0);
    CP_COMMIT();

    for (int kt = kt_lo; kt <= kt_hi; kt++) {
        const int st = (kt - kt_lo) & 1;
        const int k0 = kt * 64;
        CP_WAIT0();
        __syncthreads();

        if (kt < kt_hi) {
            load_kv(kt + 1, st ^ 1);
            CP_COMMIT();
        }

        if (k0 > qw_hi) continue;
        if (k0 + 575 <= qw_lo) continue;

        const uint32_t stb = sb + A_ST0 + st * KV_STAGE;
        const uint32_t khb = stb + ST_KH;
        const uint32_t vhb = stb + ST_VH;

        // ---- scores: Q fragments reloaded from persistent smem per ks ----
        float sacc[8][4];
#pragma unroll
        for (int nt = 0; nt < 8; nt++)
#pragma unroll
            for (int j = 0; j < 4; j++) sacc[nt][j] = 0.f;

#pragma unroll
        for (int ks = 0; ks < 8; ks++) {
            uint32_t qf[4];
            ldsm_x4(qf, qfbase + (uint32_t)(ks * 32));
#pragma unroll
            for (int ntp = 0; ntp < 4; ntp++) {
                const uint32_t br = khb + (uint32_t)((ntp * 16 + bmrow) * RQK) +
                                    (uint32_t)(ks * 32) + bcol;
                uint32_t kh4[4];
                ldsm_x4(kh4, br);
                mma16816(sacc[2 * ntp],     qf, &kh4[0]);
                mma16816(sacc[2 * ntp + 1], qf, &kh4[2]);
            }
        }

        // ---- scale (log2 domain) + mask ----
        const bool fully_valid = (k0 + 63 <= qw_lo) && (k0 >= qw_hi - (Wc - 1));
        if (fully_valid) {
#pragma unroll
            for (int nt = 0; nt < 8; nt++)
#pragma unroll
                for (int j = 0; j < 4; j++) sacc[nt][j] *= scale_eff;
        } else {
#pragma unroll
            for (int nt = 0; nt < 8; nt++) {
                const int ki0 = k0 + nt * 8 + tg * 2, ki1 = ki0 + 1;
                bool m00 = (ki0 <= qi0) && (qi0 - ki0 < Wc);
                bool m01 = (ki1 <= qi0) && (qi0 - ki1 < Wc);
                bool m10 = (ki0 <= qi1) && (qi1 - ki0 < Wc);
                bool m11 = (ki1 <= qi1) && (qi1 - ki1 < Wc);
                sacc[nt][0] = m00 ? sacc[nt][0] * scale_eff : -1e30f;
                sacc[nt][1] = m01 ? sacc[nt][1] * scale_eff : -1e30f;
                sacc[nt][2] = m10 ? sacc[nt][2] * scale_eff : -1e30f;
                sacc[nt][3] = m11 ? sacc[nt][3] * scale_eff : -1e30f;
            }
        }

        // ---- row max via shfl ----
        float mx0 = -1e30f, mx1 = -1e30f;
#pragma unroll
        for (int nt = 0; nt < 8; nt++) {
            mx0 = fmaxf(mx0, fmaxf(sacc[nt][0], sacc[nt][1]));
            mx1 = fmaxf(mx1, fmaxf(sacc[nt][2], sacc[nt][3]));
        }
        mx0 = fmaxf(mx0, __shfl_xor_sync(0xffffffffu, mx0, 1));
        mx0 = fmaxf(mx0, __shfl_xor_sync(0xffffffffu, mx0, 2));
        mx1 = fmaxf(mx1, __shfl_xor_sync(0xffffffffu, mx1, 1));
        mx1 = fmaxf(mx1, __shfl_xor_sync(0xffffffffu, mx1, 2));

        const float mn0 = fmaxf(m0, mx0);
        const float mn1 = fmaxf(m1, mx1);
        const float f0 = exp2f(m0 - mn0);
        const float f1 = exp2f(m1 - mn1);
        m0 = mn0; m1 = mn1;

        // ---- exp2 + sums ----
        float s0 = 0.f, s1 = 0.f;
#pragma unroll
        for (int nt = 0; nt < 8; nt++) {
            float p0 = (sacc[nt][0] > -1e29f) ? exp2f(sacc[nt][0] - mn0) : 0.f;
            float p1 = (sacc[nt][1] > -1e29f) ? exp2f(sacc[nt][1] - mn0) : 0.f;
            float p2 = (sacc[nt][2] > -1e29f) ? exp2f(sacc[nt][2] - mn1) : 0.f;
            float p3 = (sacc[nt][3] > -1e29f) ? exp2f(sacc[nt][3] - mn1) : 0.f;
            sacc[nt][0] = p0; sacc[nt][1] = p1; sacc[nt][2] = p2; sacc[nt][3] = p3;
            s0 += p0 + p1; s1 += p2 + p3;
        }
        s0 += __shfl_xor_sync(0xffffffffu, s0, 1);
        s0 += __shfl_xor_sync(0xffffffffu, s0, 2);
        s1 += __shfl_xor_sync(0xffffffffu, s1, 1);
        s1 += __shfl_xor_sync(0xffffffffu, s1, 2);
        l0 = l0 * f0 + s0;
        l1 = l1 * f1 + s1;

#pragma unroll
        for (int nt = 0; nt < 16; nt++) {
            oacc[nt][0] *= f0; oacc[nt][1] *= f0;
            oacc[nt][2] *= f1; oacc[nt][3] *= f1;
        }

        // ---- PV: V fragments via ldsm.trans from [s][d] layout ----
#pragma unroll
        for (int ks = 0; ks < 4; ks++) {
            uint32_t aph[4];
            aph[0] = packh2(sacc[2 * ks][0] * SCF,     sacc[2 * ks][1] * SCF);
            aph[1] = packh2(sacc[2 * ks][2] * SCF,     sacc[2 * ks][3] * SCF);
            aph[2] = packh2(sacc[2 * ks + 1][0] * SCF, sacc[2 * ks + 1][1] * SCF);
            aph[3] = packh2(sacc[2 * ks + 1][2] * SCF, sacc[2 * ks + 1][3] * SCF);
#pragma unroll
            for (int ntp = 0; ntp < 8; ntp++) {
                const uint32_t br = vhb + (uint32_t)((ks * 16 + vkrow) * RQK) +
                                    (uint32_t)(ntp * 32) + vncol;
                uint32_t vh4[4];
                ldsm_x4_t(vh4, br);
                mma16816(oacc[2 * ntp],     aph, &vh4[0]);
                mma16816(oacc[2 * ntp + 1], aph, &vh4[2]);
            }
        }
    }

    // ---- epilogue: normalize, rescale to fp16 GEMM2 A operand ----
    {
        const float linv0 = (1.0f / l0) * (1.0f / SCF);
        const float linv1 = (1.0f / l1) * (1.0f / SCF);
        const size_t tok0 = (size_t)(b * Sc + qw_lo + g);
        const size_t tok1 = tok0 + 8;
#pragma unroll
        for (int nt = 0; nt < 16; nt++) {
            const int col = h * Dc + nt * 8 + tg * 2;
            ((uint32_t*)Oh)[(tok0 * HIDc + col) >> 1] =
                packh2(oacc[nt][0] * linv0, oacc[nt][1] * linv0);
            ((uint32_t*)Oh)[(tok1 * HIDc + col) >> 1] =
                packh2(oacc[nt][2] * linv1, oacc[nt][3] * linv1);
        }
    }
}

// ---------------------------------------------------------------------------
// Launch
// ---------------------------------------------------------------------------
extern "C" void kernel_launch(void* const* d_in, const int* in_sizes, int n_in,
                              void* d_out, int out_size)
{
    const float* hidden    = (const float*)d_in[0];
    const int*   positions = (const int*)d_in[1];
    const float* w_pack    = (const float*)d_in[2];
    const float* w_o       = (const float*)d_in[3];
    const float* conv_k    = (const float*)d_in[4];
    const float* conv_v    = (const float*)d_in[5];
    float* out = (float*)d_out;

    __half *qkvh, *qh, *kh, *vh, *ah, *bh;
    cudaGetSymbolAddress((void**)&qkvh, g_qkvh);
    cudaGetSymbolAddress((void**)&qh,  g_qh);
    cudaGetSymbolAddress((void**)&kh,  g_kh);
    cudaGetSymbolAddress((void**)&vh,  g_vh);
    cudaGetSymbolAddress((void**)&ah,  g_ah);
    cudaGetSymbolAddress((void**)&bh,  g_bh);

    cudaFuncSetAttribute(gemm_mma<true>,
                         cudaFuncAttributeMaxDynamicSharedMemorySize, GEMM_SMEM);
    cudaFuncSetAttribute(gemm_mma<false>,
                         cudaFuncAttributeMaxDynamicSharedMemorySize, GEMM_SMEM);
    cudaFuncSetAttribute(attn_mma,
                         cudaFuncAttributeMaxDynamicSharedMemorySize, ATTN_SMEM);

    // ---- 1) convert inputs (hidden + w_pack) ----
    conv_in_kernel<<<NB_HID + NB_WP, 256>>>(hidden, w_pack, ah, bh);

    // ---- 2) GEMM 1: qkvh (scaled fp16) = hidden @ w_pack ----
    {
        dim3 g1(QKVF / 128, BSc / 128);
        gemm_mma<true><<<g1, 256, GEMM_SMEM>>>(ah, bh, qkvh, BSc, QKVF, HIDc);
    }

    // ---- 3) fused prep (vectorized, fp16 qkv source) ----
    fused_prep_kernel<<<NB_Q + NB_K + NB_V + NB_WO, 256>>>(
        qkvh, positions, conv_k, conv_v, w_o, qh, kh, vh, bh);

    // ---- 4) windowed attention; writes fp16 A for GEMM2 ----
    attn_mma<<<dim3(Sc / 64, Hc, Bc), 128, ATTN_SMEM>>>(qh, kh, vh, ah);

    // ---- 5) GEMM 2: out (fp32) = attn @ w_o ----
    {
        dim3 g2(HIDc / 128, BSc / 128);
        gemm_mma<false><<<g2, 256, GEMM_SMEM>>>(ah, bh, out, BSc, HIDc, HIDc);
    }
}

// round 16
// speedup vs baseline: 1.5030x; 1.5030x over previous
#include <cuda_runtime.h>
#include <cuda_fp16.h>
#include <math.h>
#include <stdint.h>

// ---------------------------------------------------------------------------
// Problem constants
// ---------------------------------------------------------------------------
#define Bc    2
#define Sc    2048
#define HIDc  4096
#define Hc    32
#define KVc   8
#define Dc    128
#define Wc    512
#define BSc   (Bc * Sc)              // 4096
#define QKVF  ((Hc + 2 * KVc) * Dc)  // 6144

// global operand scale 2^10
#define SCF      1024.0f
#define INV_SC2  (1.0f / (SCF * SCF))
#define INV_SCF  (1.0f / SCF)
#define LOG2E    1.4426950408889634f

// ---------------------------------------------------------------------------
// Scratch (static device globals -- no allocation allowed)
// ---------------------------------------------------------------------------
__device__ __half g_qkvh[(size_t)BSc * QKVF];            // scaled fp16 qkv

__device__ __half g_qh[(size_t)BSc * Hc * Dc];           // roped Q [bs][h][d]
__device__ __half g_kh[(size_t)BSc * KVc * Dc];          // K [bs][kv][d]
__device__ __half g_vh[(size_t)BSc * KVc * Dc];          // V [bs][kv][d]

__device__ __half g_ah[(size_t)BSc * HIDc];              // GEMM A [M,K]
__device__ __half g_bh[(size_t)QKVF * HIDc];             // GEMM B [K,N]

// ---------------------------------------------------------------------------
// Helpers
// ---------------------------------------------------------------------------
__device__ __forceinline__ uint32_t smem_u32(const void* p) {
    uint32_t a;
    asm("{ .reg .u64 t; cvta.to.shared.u64 t, %1; cvt.u32.u64 %0, t; }"
        : "=r"(a) : "l"(p));
    return a;
}
__device__ __forceinline__ void cp16(uint32_t smem, const void* gmem) {
    asm volatile("cp.async.cg.shared.global [%0], [%1], 16;"
                 :: "r"(smem), "l"(gmem));
}
#define CP_COMMIT() asm volatile("cp.async.commit_group;" ::: "memory")
#define CP_WAIT0()  asm volatile("cp.async.wait_group 0;" ::: "memory")

__device__ __forceinline__ void ldsm_x4(uint32_t* r, uint32_t addr) {
    asm volatile("ldmatrix.sync.aligned.m8n8.x4.shared.b16 {%0,%1,%2,%3}, [%4];"
                 : "=r"(r[0]), "=r"(r[1]), "=r"(r[2]), "=r"(r[3]) : "r"(addr));
}
__device__ __forceinline__ void ldsm_x4_t(uint32_t* r, uint32_t addr) {
    asm volatile("ldmatrix.sync.aligned.m8n8.x4.trans.shared.b16 {%0,%1,%2,%3}, [%4];"
                 : "=r"(r[0]), "=r"(r[1]), "=r"(r[2]), "=r"(r[3]) : "r"(addr));
}

// fp16 HMMA m16n8k16, fp32 accumulate
__device__ __forceinline__ void mma16816(float* d, const uint32_t* a,
                                         const uint32_t* b) {
    asm volatile(
        "mma.sync.aligned.m16n8k16.row.col.f32.f16.f16.f32 "
        "{%0,%1,%2,%3}, {%4,%5,%6,%7}, {%8,%9}, {%0,%1,%2,%3};"
        : "+f"(d[0]), "+f"(d[1]), "+f"(d[2]), "+f"(d[3])
        : "r"(a[0]), "r"(a[1]), "r"(a[2]), "r"(a[3]),
          "r"(b[0]), "r"(b[1]));
}

__device__ __forceinline__ uint32_t packh2(float x, float y) {
    __half2 h(__float2half_rn(x), __float2half_rn(y));
    return *(uint32_t*)&h;
}

// ---------------------------------------------------------------------------
// fp16 HMMA GEMM, templated epilogue (unchanged from R14 passing version)
// ---------------------------------------------------------------------------
#define GBK    64
#define AROW   144
#define BROW   272
#define MAT_A  (128 * AROW)
#define MAT_B  (64 * BROW)
#define STAGEB (MAT_A + MAT_B)
#define GEMM_SMEM (2 * STAGEB)

template <bool HOUT>
__global__ __launch_bounds__(256, 2)
void gemm_mma(const __half* __restrict__ Ah,
              const __half* __restrict__ Bh,
              void* __restrict__ Cv, int M, int N, int K)
{
    extern __shared__ char sm[];
    const uint32_t sb = smem_u32(sm);
    const int tid  = threadIdx.x;
    const int wid  = tid >> 5;
    const int lane = tid & 31;
    const int wm = wid & 3;
    const int wn = wid >> 2;
    const int g  = lane >> 2;
    const int tg = lane & 3;

    const int m0 = blockIdx.y * 128;
    const int n0 = blockIdx.x * 128;

    const uint32_t amrow = (lane & 7) + ((lane >> 3) & 1) * 8;
    const uint32_t acol  = (uint32_t)(lane >> 4) * 16;
    const uint32_t bkrow = (lane & 7) + ((lane >> 3) & 1) * 8;
    const uint32_t bncol = (uint32_t)(lane >> 4) * 16;

    auto load_stage = [&](int k0, int st) {
        const uint32_t base = sb + st * STAGEB;
#pragma unroll
        for (int hh = 0; hh < 4; hh++) {
            int unit = tid + hh * 256;
            int r = unit >> 3, u = unit & 7;
            const void* gp = Ah + (size_t)(m0 + r) * K + k0 + u * 8;
            cp16(base + r * AROW + u * 16, gp);
        }
#pragma unroll
        for (int hh = 0; hh < 4; hh++) {
            int unit = tid + hh * 256;
            int r = unit >> 4, u = unit & 15;
            const void* gp = Bh + (size_t)(k0 + r) * N + n0 + u * 8;
            cp16(base + MAT_A + r * BROW + u * 16, gp);
        }
    };

    float acc[2][8][4];
#pragma unroll
    for (int mt = 0; mt < 2; mt++)
#pragma unroll
        for (int nt = 0; nt < 8; nt++)
#pragma unroll
            for (int j = 0; j < 4; j++) acc[mt][nt][j] = 0.f;

    const int NIT = K / GBK;
    load_stage(0, 0);
    CP_COMMIT();

    for (int it = 0; it < NIT; it++) {
        CP_WAIT0();
        __syncthreads();
        const int st = it & 1;
        if (it + 1 < NIT) {
            load_stage((it + 1) * GBK, st ^ 1);
            CP_COMMIT();
        }

        const uint32_t ahb = sb + st * STAGEB;
        const uint32_t bhb = ahb + MAT_A;

#pragma unroll
        for (int ks = 0; ks < 4; ks++) {
            uint32_t ah[2][4];
#pragma unroll
            for (int mt = 0; mt < 2; mt++) {
                const uint32_t ar = ahb +
                    (uint32_t)((wm * 32 + mt * 16 + amrow) * AROW) +
                    (uint32_t)(ks * 32) + acol;
                ldsm_x4(ah[mt], ar);
            }
#pragma unroll
            for (int ntp = 0; ntp < 4; ntp++) {
                const uint32_t br = bhb +
                    (uint32_t)((ks * 16 + bkrow) * BROW) +
                    (uint32_t)((wn * 64 + ntp * 16) * 2) + bncol;
                uint32_t bh4[4];
                ldsm_x4_t(bh4, br);
#pragma unroll
                for (int mt = 0; mt < 2; mt++) {
                    mma16816(acc[mt][2 * ntp],     ah[mt], &bh4[0]);
                    mma16816(acc[mt][2 * ntp + 1], ah[mt], &bh4[2]);
                }
            }
        }
    }

#pragma unroll
    for (int mt = 0; mt < 2; mt++) {
        const int r0 = m0 + wm * 32 + mt * 16 + g;
#pragma unroll
        for (int nt = 0; nt < 8; nt++) {
            const int cc = n0 + wn * 64 + nt * 8 + tg * 2;
            if (HOUT) {
                __half* cp = (__half*)Cv;
                *(uint32_t*)(cp + (size_t)r0 * N + cc) =
                    packh2(acc[mt][nt][0] * INV_SCF, acc[mt][nt][1] * INV_SCF);
                *(uint32_t*)(cp + (size_t)(r0 + 8) * N + cc) =
                    packh2(acc[mt][nt][2] * INV_SCF, acc[mt][nt][3] * INV_SCF);
            } else {
                float* cp = (float*)Cv;
                float2 w0 = make_float2(acc[mt][nt][0] * INV_SC2,
                                        acc[mt][nt][1] * INV_SC2);
                float2 w1 = make_float2(acc[mt][nt][2] * INV_SC2,
                                        acc[mt][nt][3] * INV_SC2);
                *(float2*)(cp + (size_t)r0 * N + cc)       = w0;
                *(float2*)(cp + (size_t)(r0 + 8) * N + cc) = w1;
            }
        }
    }
}

// ---------------------------------------------------------------------------
// Fused input conversion: hidden -> g_ah, w_pack -> g_bh
// ---------------------------------------------------------------------------
#define N4_HID  (BSc * HIDc / 4)
#define NB_HID  (N4_HID / 256)               // 16384
#define N4_WP   (HIDc * QKVF / 4)
#define NB_WP   (N4_WP / 256)                // 24576

__global__ void conv_in_kernel(const float* __restrict__ hidden,
                               const float* __restrict__ w_pack,
                               __half* __restrict__ Ah,
                               __half* __restrict__ Bh)
{
    int bid = blockIdx.x;
    if (bid < NB_HID) {
        int i = bid * 256 + threadIdx.x;
        float4 v = ((const float4*)hidden)[i];
        ((uint32_t*)Ah)[i * 2 + 0] = packh2(v.x * SCF, v.y * SCF);
        ((uint32_t*)Ah)[i * 2 + 1] = packh2(v.z * SCF, v.w * SCF);
    } else {
        int i = (bid - NB_HID) * 256 + threadIdx.x;
        float4 v = ((const float4*)w_pack)[i];
        ((uint32_t*)Bh)[i * 2 + 0] = packh2(v.x * SCF, v.y * SCF);
        ((uint32_t*)Bh)[i * 2 + 1] = packh2(v.z * SCF, v.w * SCF);
    }
}

// ---------------------------------------------------------------------------
// Fused prep from scaled-fp16 qkv: rope_q(uint4) + smooth_k + smooth_v + w_o
// ---------------------------------------------------------------------------
#define NB_Q   (BSc * Hc * 8 / 256)          // 4096 (8 elems/thread)
#define NB_K   (BSc * KVc * 16 / 256)        // 2048
#define NB_V   (BSc * KVc * 16 / 256)        // 2048
#define N4_WO  (HIDc * HIDc / 4)
#define NB_WO  (N4_WO / 256)                 // 16384

__global__ void fused_prep_kernel(const __half* __restrict__ qkvh,
                                  const int* __restrict__ positions,
                                  const float* __restrict__ conv_k,
                                  const float* __restrict__ conv_v,
                                  const float* __restrict__ w_o,
                                  __half* __restrict__ Qh,
                                  __half* __restrict__ Kh,
                                  __half* __restrict__ Vh,
                                  __half* __restrict__ Bh)
{
    int bid = blockIdx.x;
    if (bid < NB_Q) {
        // ---- rope Q: 8 (i, i+64) pairs per thread via uint4 ----
        int idx = bid * 256 + threadIdx.x;      // BSc*Hc*8
        int t  = idx & 7;
        int h  = (idx >> 3) & 31;
        int bs = idx >> 8;

        const __half* src = qkvh + (size_t)bs * QKVF + h * Dc;
        uint4 a = *(const uint4*)(src + t * 8);
        uint4 c = *(const uint4*)(src + t * 8 + 64);
        const __half* ah = (const __half*)&a;
        const __half* ch = (const __half*)&c;
        float pos = (float)positions[bs];

        uint32_t o1[4], o2[4];
#pragma unroll
        for (int j2 = 0; j2 < 4; j2++) {
            float y1[2], y2[2];
#pragma unroll
            for (int j = 0; j < 2; j++) {
                int i = t * 8 + j2 * 2 + j;
                float x1 = __half2float(ah[j2 * 2 + j]);
                float x2 = __half2float(ch[j2 * 2 + j]);
                float ang = pos * exp2f((float)i * -0.2076205059304601f);
                float sn, cs;
                sincosf(ang, &sn, &cs);
                y1[j] = x1 * cs - x2 * sn;
                y2[j] = x2 * cs + x1 * sn;
            }
            o1[j2] = packh2(y1[0], y1[1]);
            o2[j2] = packh2(y2[0], y2[1]);
        }
        size_t o = (size_t)bs * (Hc * Dc) + h * Dc;
        *(uint4*)(Qh + o + t * 8)      = make_uint4(o1[0], o1[1], o1[2], o1[3]);
        *(uint4*)(Qh + o + t * 8 + 64) = make_uint4(o2[0], o2[1], o2[2], o2[3]);
    } else if (bid < NB_Q + NB_K) {
        // ---- smooth + rope K ----
        int idx = (bid - NB_Q) * 256 + threadIdx.x;   // BSc*KVc*16
        int t  = idx & 15;
        int kv = (idx >> 4) & 7;
        int bs = idx >> 7;
        int s = bs & (Sc - 1);

        const __half* src = qkvh + (size_t)bs * QKVF + Hc * Dc + kv * Dc;
        uint2 a = *(const uint2*)(src + t * 4);
        uint2 c = *(const uint2*)(src + t * 4 + 64);
        uint2 pa = make_uint2(0, 0), pc = make_uint2(0, 0);
        if (s > 0) {
            pa = *(const uint2*)(src - QKVF + t * 4);
            pc = *(const uint2*)(src - QKVF + t * 4 + 64);
        }
        const __half* ah = (const __half*)&a;
        const __half* ch = (const __half*)&c;
        const __half* pah = (const __half*)&pa;
        const __half* pch = (const __half*)&pc;
        float f0 = conv_k[kv], f1 = conv_k[KVc + kv];
        float pos = (float)positions[bs];

        uint32_t o1[2], o2[2];
#pragma unroll
        for (int j2 = 0; j2 < 2; j2++) {
            float y1[2], y2[2];
#pragma unroll
            for (int j = 0; j < 2; j++) {
                int i = t * 4 + j2 * 2 + j;
                float x1 = __half2float(ah[j2 * 2 + j]) * f1 +
                           __half2float(pah[j2 * 2 + j]) * f0;
                float x2 = __half2float(ch[j2 * 2 + j]) * f1 +
                           __half2float(pch[j2 * 2 + j]) * f0;
                float ang = pos * exp2f((float)i * -0.2076205059304601f);
                float sn, cs;
                sincosf(ang, &sn, &cs);
                y1[j] = x1 * cs - x2 * sn;
                y2[j] = x2 * cs + x1 * sn;
            }
            o1[j2] = packh2(y1[0], y1[1]);
            o2[j2] = packh2(y2[0], y2[1]);
        }
        size_t o = ((size_t)bs * KVc + kv) * Dc;
        *(uint2*)(Kh + o + t * 4)      = make_uint2(o1[0], o1[1]);
        *(uint2*)(Kh + o + t * 4 + 64) = make_uint2(o2[0], o2[1]);
    } else if (bid < NB_Q + NB_K + NB_V) {
        // ---- smooth V: 8 elems per thread ----
        int idx = (bid - NB_Q - NB_K) * 256 + threadIdx.x;   // BSc*KVc*16
        int t  = idx & 15;
        int kv = (idx >> 4) & 7;
        int bs = idx >> 7;
        int s = bs & (Sc - 1);

        const __half* src = qkvh + (size_t)bs * QKVF + (Hc + KVc) * Dc + kv * Dc;
        uint4 cu = *(const uint4*)(src + t * 8);
        uint4 pu = make_uint4(0, 0, 0, 0);
        if (s > 0) pu = *(const uint4*)(src - QKVF + t * 8);
        const __half* chh = (const __half*)&cu;
        const __half* phh = (const __half*)&pu;
        float f0 = conv_v[kv], f1 = conv_v[KVc + kv];

        uint32_t ow[4];
#pragma unroll
        for (int j2 = 0; j2 < 4; j2++) {
            float v0 = __half2float(chh[j2 * 2])     * f1 +
                       __half2float(phh[j2 * 2])     * f0;
            float v1 = __half2float(chh[j2 * 2 + 1]) * f1 +
                       __half2float(phh[j2 * 2 + 1]) * f0;
            ow[j2] = packh2(v0, v1);
        }
        size_t o = ((size_t)bs * KVc + kv) * Dc + t * 8;
        *(uint4*)(Vh + o) = make_uint4(ow[0], ow[1], ow[2], ow[3]);
    } else {
        // ---- w_o conversion ----
        int i = (bid - NB_Q - NB_K - NB_V) * 256 + threadIdx.x;
        float4 v = ((const float4*)w_o)[i];
        ((uint32_t*)Bh)[i * 2 + 0] = packh2(v.x * SCF, v.y * SCF);
        ((uint32_t*)Bh)[i * 2 + 1] = packh2(v.z * SCF, v.w * SCF);
    }
}

// ---------------------------------------------------------------------------
// Register-resident windowed flash attention (R14 passing configuration:
// persistent Q fragments, __launch_bounds__(128, 2))
// ---------------------------------------------------------------------------
#define RQK  272

#define A_QH   0
#define A_ST0  (A_QH + 64 * RQK)
#define KV_STAGE (2 * 64 * RQK)
#define ST_KH  0
#define ST_VH  (64 * RQK)
#define ATTN_SMEM (A_ST0 + 2 * KV_STAGE)            // 87040

__global__ __launch_bounds__(128, 2)
void attn_mma(const __half* __restrict__ Qh,
              const __half* __restrict__ Kh, const __half* __restrict__ Vh,
              __half* __restrict__ Oh)
{
    extern __shared__ char sm[];
    const uint32_t sb = smem_u32(sm);

    const int tid  = threadIdx.x;
    const int w    = tid >> 5;
    const int lane = tid & 31;
    const int g  = lane >> 2;
    const int tg = lane & 3;

    const int qt = blockIdx.x, h = blockIdx.y, b = blockIdx.z;
    const int q0 = qt * 64;
    const int kvh = h >> 2;
    const float scale_eff = 0.08838834764831845f * INV_SC2 * LOG2E;

    const uint32_t bmrow = (lane & 7) + (uint32_t)(lane >> 4) * 8;
    const uint32_t bcol  = ((lane >> 3) & 1) * 16;
    const uint32_t vkrow = (lane & 7) + ((lane >> 3) & 1) * 8;
    const uint32_t vncol = (uint32_t)(lane >> 4) * 16;

    {
        const size_t qbase = ((size_t)(b * Sc + q0) * Hc + h) * Dc;
#pragma unroll
        for (int hh = 0; hh < 8; hh++) {
            int idx = tid + hh * 128;
            int r = idx >> 4, u = idx & 15;
            const size_t go = qbase + (size_t)r * (Hc * Dc) + u * 8;
            cp16(sb + A_QH + r * RQK + u * 16, Qh + go);
        }
    }

    const size_t kvbase = ((size_t)b * Sc * KVc + kvh) * Dc;
    auto load_kv = [&](int kt, int st) {
        const int k0 = kt * 64;
        const uint32_t stb = sb + A_ST0 + st * KV_STAGE;
#pragma unroll
        for (int hh = 0; hh < 8; hh++) {
            int idx = tid + hh * 128;
            int r = idx >> 4, u = idx & 15;
            const size_t go = kvbase + (size_t)(k0 + r) * (KVc * Dc) + u * 8;
            cp16(stb + ST_KH + r * RQK + u * 16, Kh + go);
            cp16(stb + ST_VH + r * RQK + u * 16, Vh + go);
        }
    };

    float m0 = -1e30f, m1 = -1e30f, l0 = 0.f, l1 = 0.f;
    float oacc[16][4];
#pragma unroll
    for (int nt = 0; nt < 16; nt++)
#pragma unroll
        for (int j = 0; j < 4; j++) oacc[nt][j] = 0.f;

    const int qw_lo = q0 + w * 16;
    const int qw_hi = qw_lo + 15;
    const int qi0 = qw_lo + g;
    const int qi1 = qi0 + 8;

    int kt_lo = qt - 8; if (kt_lo < 0) kt_lo = 0;
    const int kt_hi = qt;

    load_kv(kt_lo, 0);
    CP_COMMIT();

    uint32_t qfh[8][4];

    for (int kt = kt_lo; kt <= kt_hi; kt++) {
        const int st = (kt - kt_lo) & 1;
        const int k0 = kt * 64;
        CP_WAIT0();
        __syncthreads();

        if (kt == kt_lo) {
            const uint32_t amrow = (lane & 7) + ((lane >> 3) & 1) * 8;
            const uint32_t acol  = (uint32_t)(lane >> 4) * 16;
#pragma unroll
            for (int ks = 0; ks < 8; ks++) {
                const uint32_t ar = (uint32_t)((w * 16 + amrow) * RQK) +
                                    (uint32_t)(ks * 32) + acol;
                ldsm_x4(qfh[ks], sb + A_QH + ar);
            }
        }

        if (kt < kt_hi) {
            load_kv(kt + 1, st ^ 1);
            CP_COMMIT();
        }

        if (k0 > qw_hi) continue;
        if (k0 + 575 <= qw_lo) continue;

        const uint32_t stb = sb + A_ST0 + st * KV_STAGE;
        const uint32_t khb = stb + ST_KH;
        const uint32_t vhb = stb + ST_VH;

        float sacc[8][4];
#pragma unroll
        for (int nt = 0; nt < 8; nt++)
#pragma unroll
            for (int j = 0; j < 4; j++) sacc[nt][j] = 0.f;

#pragma unroll
        for (int ks = 0; ks < 8; ks++) {
#pragma unroll
            for (int ntp = 0; ntp < 4; ntp++) {
                const uint32_t br = khb + (uint32_t)((ntp * 16 + bmrow) * RQK) +
                                    (uint32_t)(ks * 32) + bcol;
                uint32_t kh4[4];
                ldsm_x4(kh4, br);
                mma16816(sacc[2 * ntp],     qfh[ks], &kh4[0]);
                mma16816(sacc[2 * ntp + 1], qfh[ks], &kh4[2]);
            }
        }

        const bool fully_valid = (k0 + 63 <= qw_lo) && (k0 >= qw_hi - (Wc - 1));
        if (fully_valid) {
#pragma unroll
            for (int nt = 0; nt < 8; nt++)
#pragma unroll
                for (int j = 0; j < 4; j++) sacc[nt][j] *= scale_eff;
        } else {
#pragma unroll
            for (int nt = 0; nt < 8; nt++) {
                const int ki0 = k0 + nt * 8 + tg * 2, ki1 = ki0 + 1;
                bool m00 = (ki0 <= qi0) && (qi0 - ki0 < Wc);
                bool m01 = (ki1 <= qi0) && (qi0 - ki1 < Wc);
                bool m10 = (ki0 <= qi1) && (qi1 - ki0 < Wc);
                bool m11 = (ki1 <= qi1) && (qi1 - ki1 < Wc);
                sacc[nt][0] = m00 ? sacc[nt][0] * scale_eff : -1e30f;
                sacc[nt][1] = m01 ? sacc[nt][1] * scale_eff : -1e30f;
                sacc[nt][2] = m10 ? sacc[nt][2] * scale_eff : -1e30f;
                sacc[nt][3] = m11 ? sacc[nt][3] * scale_eff : -1e30f;
            }
        }

        float mx0 = -1e30f, mx1 = -1e30f;
#pragma unroll
        for (int nt = 0; nt < 8; nt++) {
            mx0 = fmaxf(mx0, fmaxf(sacc[nt][0], sacc[nt][1]));
            mx1 = fmaxf(mx1, fmaxf(sacc[nt][2], sacc[nt][3]));
        }
        mx0 = fmaxf(mx0, __shfl_xor_sync(0xffffffffu, mx0, 1));
        mx0 = fmaxf(mx0, __shfl_xor_sync(0xffffffffu, mx0, 2));
        mx1 = fmaxf(mx1, __shfl_xor_sync(0xffffffffu, mx1, 1));
        mx1 = fmaxf(mx1, __shfl_xor_sync(0xffffffffu, mx1, 2));

        const float mn0 = fmaxf(m0, mx0);
        const float mn1 = fmaxf(m1, mx1);
        const float f0 = exp2f(m0 - mn0);
        const float f1 = exp2f(m1 - mn1);
        m0 = mn0; m1 = mn1;

        float s0 = 0.f, s1 = 0.f;
#pragma unroll
        for (int nt = 0; nt < 8; nt++) {
            float p0 = (sacc[nt][0] > -1e29f) ? exp2f(sacc[nt][0] - mn0) : 0.f;
            float p1 = (sacc[nt][1] > -1e29f) ? exp2f(sacc[nt][1] - mn0) : 0.f;
            float p2 = (sacc[nt][2] > -1e29f) ? exp2f(sacc[nt][2] - mn1) : 0.f;
            float p3 = (sacc[nt][3] > -1e29f) ? exp2f(sacc[nt][3] - mn1) : 0.f;
            sacc[nt][0] = p0; sacc[nt][1] = p1; sacc[nt][2] = p2; sacc[nt][3] = p3;
            s0 += p0 + p1; s1 += p2 + p3;
        }
        s0 += __shfl_xor_sync(0xffffffffu, s0, 1);
        s0 += __shfl_xor_sync(0xffffffffu, s0, 2);
        s1 += __shfl_xor_sync(0xffffffffu, s1, 1);
        s1 += __shfl_xor_sync(0xffffffffu, s1, 2);
        l0 = l0 * f0 + s0;
        l1 = l1 * f1 + s1;

#pragma unroll
        for (int nt = 0; nt < 16; nt++) {
            oacc[nt][0] *= f0; oacc[nt][1] *= f0;
            oacc[nt][2] *= f1; oacc[nt][3] *= f1;
        }

#pragma unroll
        for (int ks = 0; ks < 4; ks++) {
            uint32_t aph[4];
            aph[0] = packh2(sacc[2 * ks][0] * SCF,     sacc[2 * ks][1] * SCF);
            aph[1] = packh2(sacc[2 * ks][2] * SCF,     sacc[2 * ks][3] * SCF);
            aph[2] = packh2(sacc[2 * ks + 1][0] * SCF, sacc[2 * ks + 1][1] * SCF);
            aph[3] = packh2(sacc[2 * ks + 1][2] * SCF, sacc[2 * ks + 1][3] * SCF);
#pragma unroll
            for (int ntp = 0; ntp < 8; ntp++) {
                const uint32_t br = vhb + (uint32_t)((ks * 16 + vkrow) * RQK) +
                                    (uint32_t)(ntp * 32) + vncol;
                uint32_t vh4[4];
                ldsm_x4_t(vh4, br);
                mma16816(oacc[2 * ntp],     aph, &vh4[0]);
                mma16816(oacc[2 * ntp + 1], aph, &vh4[2]);
            }
        }
    }

    {
        const float linv0 = (1.0f / l0) * (1.0f / SCF);
        const float linv1 = (1.0f / l1) * (1.0f / SCF);
        const size_t tok0 = (size_t)(b * Sc + qw_lo + g);
        const size_t tok1 = tok0 + 8;
#pragma unroll
        for (int nt = 0; nt < 16; nt++) {
            const int col = h * Dc + nt * 8 + tg * 2;
            ((uint32_t*)Oh)[(tok0 * HIDc + col) >> 1] =
                packh2(oacc[nt][0] * linv0, oacc[nt][1] * linv0);
            ((uint32_t*)Oh)[(tok1 * HIDc + col) >> 1] =
                packh2(oacc[nt][2] * linv1, oacc[nt][3] * linv1);
        }
    }
}

// ---------------------------------------------------------------------------
// Launch
// ---------------------------------------------------------------------------
extern "C" void kernel_launch(void* const* d_in, const int* in_sizes, int n_in,
                              void* d_out, int out_size)
{
    const float* hidden    = (const float*)d_in[0];
    const int*   positions = (const int*)d_in[1];
    const float* w_pack    = (const float*)d_in[2];
    const float* w_o       = (const float*)d_in[3];
    const float* conv_k    = (const float*)d_in[4];
    const float* conv_v    = (const float*)d_in[5];
    float* out = (float*)d_out;

    __half *qkvh, *qh, *kh, *vh, *ah, *bh;
    cudaGetSymbolAddress((void**)&qkvh, g_qkvh);
    cudaGetSymbolAddress((void**)&qh,  g_qh);
    cudaGetSymbolAddress((void**)&kh,  g_kh);
    cudaGetSymbolAddress((void**)&vh,  g_vh);
    cudaGetSymbolAddress((void**)&ah,  g_ah);
    cudaGetSymbolAddress((void**)&bh,  g_bh);

    cudaFuncSetAttribute(gemm_mma<true>,
                         cudaFuncAttributeMaxDynamicSharedMemorySize, GEMM_SMEM);
    cudaFuncSetAttribute(gemm_mma<false>,
                         cudaFuncAttributeMaxDynamicSharedMemorySize, GEMM_SMEM);
    cudaFuncSetAttribute(attn_mma,
                         cudaFuncAttributeMaxDynamicSharedMemorySize, ATTN_SMEM);

    // ---- 1) convert inputs (hidden + w_pack) ----
    conv_in_kernel<<<NB_HID + NB_WP, 256>>>(hidden, w_pack, ah, bh);

    // ---- 2) GEMM 1: qkvh (scaled fp16) = hidden @ w_pack ----
    {
        dim3 g1(QKVF / 128, BSc / 128);
        gemm_mma<true><<<g1, 256, GEMM_SMEM>>>(ah, bh, qkvh, BSc, QKVF, HIDc);
    }

    // ---- 3) fused prep (vectorized, fp16 qkv source) ----
    fused_prep_kernel<<<NB_Q + NB_K + NB_V + NB_WO, 256>>>(
        qkvh, positions, conv_k, conv_v, w_o, qh, kh, vh, bh);

    // ---- 4) windowed attention; writes fp16 A for GEMM2 ----
    attn_mma<<<dim3(Sc / 64, Hc, Bc), 128, ATTN_SMEM>>>(qh, kh, vh, ah);

    // ---- 5) GEMM 2: out (fp32) = attn @ w_o ----
    {
        dim3 g2(HIDc / 128, BSc / 128);
        gemm_mma<false><<<g2, 256, GEMM_SMEM>>>(ah, bh, out, BSc, HIDc, HIDc);
    }
}